// round 8
// baseline (speedup 1.0000x reference)
#include <cuda_runtime.h>
#include <cstdint>

// PLE encoding, 1M x 64 f32 out (256 MB) -> store-bound.
// R7: route stores through the bulk-async engine (UBLKCP) instead of STG.
// Evidence: L1% == DRAM% every round (STG wavefront path co-binds at ~56%);
// occupancy fix (R5) falsified the warp-count theory. So: compute 8KB tiles
// (32 elems x 64 bins) into SMEM, drain with cp.async.bulk.global.shared::cta
// (double-buffered, <=2 in flight/block). Math: r = clamp((x-lo)*inv, b) with
// fma.rn.sat for interior bins (verified identity, rel_err ~3e-7).

#define N_BINS 64
#define TILE_ELEMS 32
#define TILE_FLOATS (TILE_ELEMS * N_BINS)      // 2048
#define TILE_BYTES (TILE_FLOATS * 4)           // 8192

__device__ __forceinline__ float fma_sat(float a, float b, float c) {
    float r;
    asm("fma.rn.sat.f32 %0, %1, %2, %3;" : "=f"(r) : "f"(a), "f"(b), "f"(c));
    return r;
}

__device__ __forceinline__ uint32_t smem_u32(const void* p) {
    return (uint32_t)__cvta_generic_to_shared(p);
}

__global__ __launch_bounds__(256) void ple_kernel(
    const float* __restrict__ x,
    const float* __restrict__ bins,
    float* __restrict__ out,
    int batch)
{
    __shared__ alignas(128) float buf[2][TILE_FLOATS];

    const int tid     = threadIdx.x;
    const int elem_in = tid >> 3;          // 0..31: element within tile
    const int j0      = (tid & 7) << 3;    // 8-bin group

    const float NEG_INF = __int_as_float(0xff800000u);
    const float POS_INF = __int_as_float(0x7f800000u);

    // Per-thread bin constants (8 bins).
    float inv[8], c[8];
#pragma unroll
    for (int k = 0; k < 8; k++) {
        const int j  = j0 + k;
        const float lo = __ldg(&bins[j]);
        const float hi = __ldg(&bins[j + 1]);
        const float iv = 1.0f / (hi - lo);
        inv[k] = iv;
        c[k]   = -lo * iv;
    }
    const float lob0 = (j0 == 0)              ? NEG_INF : 0.0f;
    const float hib7 = (j0 + 7 == N_BINS - 1) ? POS_INF : 1.0f;

    const int ntiles = (batch + TILE_ELEMS - 1) / TILE_ELEMS;
    const uint32_t s_base0 = smem_u32(&buf[0][0]);
    const uint32_t s_base1 = smem_u32(&buf[1][0]);
    const uint32_t s_off   = (uint32_t)(elem_in * N_BINS + j0) * 4u;

    int parity = 0;
    for (int tile = blockIdx.x; tile < ntiles; tile += gridDim.x, parity ^= 1) {
        const int i = tile * TILE_ELEMS + elem_in;

        // 1) compute into registers (no smem dependency yet)
        float r[8];
        float xv = 0.0f;
        if (i < batch) xv = __ldg(&x[i]);
        r[0] = fminf(fmaxf(fmaf(xv, inv[0], c[0]), lob0), 1.0f);
#pragma unroll
        for (int k = 1; k < 7; k++)
            r[k] = fma_sat(xv, inv[k], c[k]);
        r[7] = fminf(fmaxf(fmaf(xv, inv[7], c[7]), 0.0f), hib7);

        // 2) ensure the buffer we're about to overwrite has been fully read
        //    by the bulk engine (issued 2 iterations ago).
        if (tid == 0) {
            asm volatile("cp.async.bulk.wait_group.read 1;" ::: "memory");
        }
        __syncthreads();

        // 3) stage tile into smem (2x STS.128 per thread, contiguous 32B)
        const uint32_t s = (parity ? s_base1 : s_base0) + s_off;
        asm volatile("st.shared.v4.f32 [%0], {%1, %2, %3, %4};"
                     :: "r"(s), "f"(r[0]), "f"(r[1]), "f"(r[2]), "f"(r[3]));
        asm volatile("st.shared.v4.f32 [%0], {%1, %2, %3, %4};"
                     :: "r"(s + 16), "f"(r[4]), "f"(r[5]), "f"(r[6]), "f"(r[7]));
        __syncthreads();

        // 4) elected thread drains the tile via bulk-async store
        if (tid == 0) {
            const int elems_here = min(TILE_ELEMS, batch - tile * TILE_ELEMS);
            const uint32_t bytes = (uint32_t)elems_here * N_BINS * 4u;
            float* dst = out + (long long)tile * TILE_FLOATS;
            asm volatile("fence.proxy.async.shared::cta;" ::: "memory");
            asm volatile(
                "cp.async.bulk.global.shared::cta.bulk_group [%0], [%1], %2;"
                :: "l"(dst), "r"(parity ? s_base1 : s_base0), "r"(bytes)
                : "memory");
            asm volatile("cp.async.bulk.commit_group;" ::: "memory");
        }
        // no trailing sync needed: next iteration's wait_group + syncthreads
        // protects the buffer before anyone overwrites it.
    }
    // Outstanding bulk stores complete before kernel exit per the async model.
}

extern "C" void kernel_launch(void* const* d_in, const int* in_sizes, int n_in,
                              void* d_out, int out_size)
{
    const float* x    = (const float*)d_in[0];
    const float* bins = (const float*)d_in[1];
    float* out        = (float*)d_out;

    const int batch   = in_sizes[0];   // 1,000,000
    const int threads = 256;
    const int blocks  = 2048;          // R3-best grid shape; ~15 tiles/block

    ple_kernel<<<blocks, threads>>>(x, bins, out, batch);
}

// round 9
// speedup vs baseline: 1.4427x; 1.4427x over previous
#include <cuda_runtime.h>
#include <cstdint>

// PLE encoding, 1M x 64 f32 out (256 MB) -> HBM-store-bound.
// r[j] = clamp((x-lo[j])*inv[j], b) ; interior bins [0,1] (fma.rn.sat),
// bin 0 [-inf,1], bin 63 [0,+inf]. (Identity verified, rel_err ~3e-7.)
//
// R8 = R3 (best, 44.1us: unroll 4, STG.256, register bin constants) with
// exact one-wave grid. R3 ran 2.25 waves of equal-duration blocks -> final
// 224-block wave at ~25% utilization. Here: 6 blocks/SM x 152 SMs = 912
// blocks, grid-stride, no tail. Also 32-bit addressing (256MB fits u32).

#define N_BINS 64

__device__ __forceinline__ float fma_sat(float a, float b, float c) {
    float r;
    asm("fma.rn.sat.f32 %0, %1, %2, %3;" : "=f"(r) : "f"(a), "f"(b), "f"(c));
    return r;
}

__device__ __forceinline__ void stg256(float* p,
                                       float r0, float r1, float r2, float r3,
                                       float r4, float r5, float r6, float r7)
{
    asm volatile(
        "st.global.v8.f32 [%0], {%1, %2, %3, %4, %5, %6, %7, %8};"
        :: "l"(p),
           "f"(r0), "f"(r1), "f"(r2), "f"(r3),
           "f"(r4), "f"(r5), "f"(r6), "f"(r7)
        : "memory");
}

__global__ __launch_bounds__(256, 6) void ple_kernel(
    const float* __restrict__ x,
    const float* __restrict__ bins,
    float* __restrict__ out,
    int batch)
{
    const int t       = blockIdx.x * blockDim.x + threadIdx.x;
    const int lane8   = t & 7;          // which 8-bin group of the row
    const int group0  = t >> 3;         // starting element index
    const int ngroups = (gridDim.x * blockDim.x) >> 3;
    const int j0      = lane8 << 3;

    const float NEG_INF = __int_as_float(0xff800000u);
    const float POS_INF = __int_as_float(0x7f800000u);

    // Per-thread bin constants (8 bins), register-resident.
    float inv[8], c[8];
#pragma unroll
    for (int k = 0; k < 8; k++) {
        const int j  = j0 + k;
        const float lo = __ldg(&bins[j]);
        const float hi = __ldg(&bins[j + 1]);
        const float iv = 1.0f / (hi - lo);
        inv[k] = iv;
        c[k]   = -lo * iv;                       // v = x*inv + c
    }
    const float lob0 = (j0 == 0)              ? NEG_INF : 0.0f;  // k==0
    const float hib7 = (j0 + 7 == N_BINS - 1) ? POS_INF : 1.0f;  // k==7

    // 32-bit byte offsets: batch*64*4 = 256MB < 4GB.
    char* outb = (char*)out;
    uint32_t off    = ((uint32_t)group0 * N_BINS + (uint32_t)j0) * 4u;
    const uint32_t dstep = (uint32_t)ngroups * N_BINS * 4u;

#pragma unroll 4
    for (int i = group0; i < batch; i += ngroups, off += dstep) {
        const float xv = __ldg(&x[i]);
        float r[8];
        r[0] = fminf(fmaxf(fmaf(xv, inv[0], c[0]), lob0), 1.0f);
#pragma unroll
        for (int k = 1; k < 7; k++)
            r[k] = fma_sat(xv, inv[k], c[k]);
        r[7] = fminf(fmaxf(fmaf(xv, inv[7], c[7]), 0.0f), hib7);

        stg256((float*)(outb + off),
               r[0], r[1], r[2], r[3], r[4], r[5], r[6], r[7]);
    }
}

extern "C" void kernel_launch(void* const* d_in, const int* in_sizes, int n_in,
                              void* d_out, int out_size)
{
    const float* x    = (const float*)d_in[0];
    const float* bins = (const float*)d_in[1];
    float* out        = (float*)d_out;

    const int batch   = in_sizes[0];   // 1,000,000
    const int threads = 256;
    // Exactly one wave: 6 blocks/SM (regs<=42 via launch_bounds) x 152 SMs.
    const int blocks  = 6 * 152;

    ple_kernel<<<blocks, threads>>>(x, bins, out, batch);
}